// round 3
// baseline (speedup 1.0000x reference)
#include <cuda_runtime.h>

// LIF neuron Euler step (TemporalReceptiveField), pure elementwise.
// x, v0, i0: (B=16, C=64, H=128, W=128) fp32.  ps: (64,) fp32 per-channel tau.
// Outputs concatenated in d_out: [z | v_new | i_new], each B*C*H*W fp32.
//
// v_decayed = v0 + DT*tau*(V_LEAK - v0 + i0)   (V_LEAK = 0)
// i_decayed = i0 - DT*TAU_SYN_INV*i0
// z         = (v_decayed - V_TH > 0) ? 1 : 0   (V_TH = 1)
// v_new     = (1-z)*v_decayed + z*V_RESET      (V_RESET = 0)
// i_new     = i_decayed + x

#define DT           0.001f
#define TAU_SYN_INV  200.0f
#define V_TH         1.0f

static constexpr int N_ELEMS = 16 * 64 * 128 * 128;   // 16,777,216
static constexpr int N4      = N_ELEMS / 4;           // 4,194,304 float4s
static constexpr int HW4     = (128 * 128) / 4;       // 4096 float4s per channel plane
static constexpr int THREADS = 256;
static constexpr int BLOCKS  = N4 / THREADS;          // 16384

__global__ __launch_bounds__(THREADS)
void lif_step_kernel(const float4* __restrict__ x,
                     const float4* __restrict__ v0,
                     const float4* __restrict__ i0,
                     const float*  __restrict__ ps,
                     float4* __restrict__ z_out,
                     float4* __restrict__ v_out,
                     float4* __restrict__ i_out)
{
    const int i = blockIdx.x * THREADS + threadIdx.x;   // exact cover, no bounds check needed
    // channel = (element_index / (H*W)) % C  ->  (i / HW4) % 64
    const int c = (i >> 12) & 63;                        // HW4 = 4096 = 2^12
    const float dt_tau = DT * __ldg(ps + c);
    const float syn_k  = DT * TAU_SYN_INV;               // 0.2f (computed as ref does)

    const float4 xv = x[i];
    const float4 vv = v0[i];
    const float4 iv = i0[i];

    float4 zr, vr, ir;

    {
        float vd = fmaf(dt_tau, iv.x - vv.x, vv.x);
        float z  = (vd - V_TH > 0.0f) ? 1.0f : 0.0f;
        zr.x = z;  vr.x = (z > 0.0f) ? 0.0f : vd;
        ir.x = (iv.x - syn_k * iv.x) + xv.x;
    }
    {
        float vd = fmaf(dt_tau, iv.y - vv.y, vv.y);
        float z  = (vd - V_TH > 0.0f) ? 1.0f : 0.0f;
        zr.y = z;  vr.y = (z > 0.0f) ? 0.0f : vd;
        ir.y = (iv.y - syn_k * iv.y) + xv.y;
    }
    {
        float vd = fmaf(dt_tau, iv.z - vv.z, vv.z);
        float z  = (vd - V_TH > 0.0f) ? 1.0f : 0.0f;
        zr.z = z;  vr.z = (z > 0.0f) ? 0.0f : vd;
        ir.z = (iv.z - syn_k * iv.z) + xv.z;
    }
    {
        float vd = fmaf(dt_tau, iv.w - vv.w, vv.w);
        float z  = (vd - V_TH > 0.0f) ? 1.0f : 0.0f;
        zr.w = z;  vr.w = (z > 0.0f) ? 0.0f : vd;
        ir.w = (iv.w - syn_k * iv.w) + xv.w;
    }

    z_out[i] = zr;
    v_out[i] = vr;
    i_out[i] = ir;
}

extern "C" void kernel_launch(void* const* d_in, const int* in_sizes, int n_in,
                              void* d_out, int out_size)
{
    const float4* x  = (const float4*)d_in[0];
    const float4* v0 = (const float4*)d_in[1];
    const float4* i0 = (const float4*)d_in[2];
    const float*  ps = (const float*)d_in[3];

    float* out = (float*)d_out;
    float4* z_out = (float4*)(out);
    float4* v_out = (float4*)(out + N_ELEMS);
    float4* i_out = (float4*)(out + 2 * N_ELEMS);

    lif_step_kernel<<<BLOCKS, THREADS>>>(x, v0, i0, ps, z_out, v_out, i_out);
}

// round 4
// speedup vs baseline: 1.0060x; 1.0060x over previous
#include <cuda_runtime.h>

// LIF neuron Euler step (TemporalReceptiveField), pure elementwise, HBM-bound.
// R3: 2x float4 per thread (MLP_p1=6) + streaming cache hints (__ldcs/__stcs).

#define DT           0.001f
#define TAU_SYN_INV  200.0f
#define V_TH         1.0f

static constexpr int N_ELEMS = 16 * 64 * 128 * 128;   // 16,777,216
static constexpr int N4      = N_ELEMS / 4;           // 4,194,304 float4s
static constexpr int THREADS = 256;
static constexpr int PER_BLK = THREADS * 2;           // 512 float4s per block
static constexpr int BLOCKS  = N4 / PER_BLK;          // 8192

__device__ __forceinline__ void lif4(const float4 xv, const float4 vv, const float4 iv,
                                     const float dt_tau, const float syn_k,
                                     float4& zr, float4& vr, float4& ir)
{
    {
        float vd = fmaf(dt_tau, iv.x - vv.x, vv.x);
        float z  = (vd - V_TH > 0.0f) ? 1.0f : 0.0f;
        zr.x = z;  vr.x = (z > 0.0f) ? 0.0f : vd;
        ir.x = (iv.x - syn_k * iv.x) + xv.x;
    }
    {
        float vd = fmaf(dt_tau, iv.y - vv.y, vv.y);
        float z  = (vd - V_TH > 0.0f) ? 1.0f : 0.0f;
        zr.y = z;  vr.y = (z > 0.0f) ? 0.0f : vd;
        ir.y = (iv.y - syn_k * iv.y) + xv.y;
    }
    {
        float vd = fmaf(dt_tau, iv.z - vv.z, vv.z);
        float z  = (vd - V_TH > 0.0f) ? 1.0f : 0.0f;
        zr.z = z;  vr.z = (z > 0.0f) ? 0.0f : vd;
        ir.z = (iv.z - syn_k * iv.z) + xv.z;
    }
    {
        float vd = fmaf(dt_tau, iv.w - vv.w, vv.w);
        float z  = (vd - V_TH > 0.0f) ? 1.0f : 0.0f;
        zr.w = z;  vr.w = (z > 0.0f) ? 0.0f : vd;
        ir.w = (iv.w - syn_k * iv.w) + xv.w;
    }
}

__global__ __launch_bounds__(THREADS)
void lif_step_kernel(const float4* __restrict__ x,
                     const float4* __restrict__ v0,
                     const float4* __restrict__ i0,
                     const float*  __restrict__ ps,
                     float4* __restrict__ z_out,
                     float4* __restrict__ v_out,
                     float4* __restrict__ i_out)
{
    const int i0idx = blockIdx.x * PER_BLK + threadIdx.x;  // exact cover
    const int i1idx = i0idx + THREADS;

    // Front-batch all 6 loads (streaming hint: no reuse, evict-first).
    const float4 xv0 = __ldcs(x  + i0idx);
    const float4 vv0 = __ldcs(v0 + i0idx);
    const float4 iv0 = __ldcs(i0 + i0idx);
    const float4 xv1 = __ldcs(x  + i1idx);
    const float4 vv1 = __ldcs(v0 + i1idx);
    const float4 iv1 = __ldcs(i0 + i1idx);

    // channel = (element_index / (H*W)) % C  ->  (float4_index >> 12) & 63
    const float syn_k   = DT * TAU_SYN_INV;  // 0.2f, matching ref op order
    const float dt_tau0 = DT * __ldg(ps + ((i0idx >> 12) & 63));
    const float dt_tau1 = DT * __ldg(ps + ((i1idx >> 12) & 63));

    float4 zr0, vr0, ir0, zr1, vr1, ir1;
    lif4(xv0, vv0, iv0, dt_tau0, syn_k, zr0, vr0, ir0);
    lif4(xv1, vv1, iv1, dt_tau1, syn_k, zr1, vr1, ir1);

    __stcs(z_out + i0idx, zr0);
    __stcs(v_out + i0idx, vr0);
    __stcs(i_out + i0idx, ir0);
    __stcs(z_out + i1idx, zr1);
    __stcs(v_out + i1idx, vr1);
    __stcs(i_out + i1idx, ir1);
}

extern "C" void kernel_launch(void* const* d_in, const int* in_sizes, int n_in,
                              void* d_out, int out_size)
{
    const float4* x  = (const float4*)d_in[0];
    const float4* v0 = (const float4*)d_in[1];
    const float4* i0 = (const float4*)d_in[2];
    const float*  ps = (const float*)d_in[3];

    float* out = (float*)d_out;
    float4* z_out = (float4*)(out);
    float4* v_out = (float4*)(out + N_ELEMS);
    float4* i_out = (float4*)(out + 2 * N_ELEMS);

    lif_step_kernel<<<BLOCKS, THREADS>>>(x, v0, i0, ps, z_out, v_out, i_out);
}

// round 5
// speedup vs baseline: 1.0146x; 1.0086x over previous
#include <cuda_runtime.h>

// LIF neuron Euler step (TemporalReceptiveField), pure elementwise, HBM-bound.
// R4: 4x float4 per thread (12 front-batched LDG.128, MLP_p1~12) + streaming hints.

#define DT           0.001f
#define TAU_SYN_INV  200.0f
#define V_TH         1.0f

static constexpr int N_ELEMS = 16 * 64 * 128 * 128;   // 16,777,216
static constexpr int N4      = N_ELEMS / 4;           // 4,194,304 float4s
static constexpr int THREADS = 256;
static constexpr int UNROLL  = 4;
static constexpr int PER_BLK = THREADS * UNROLL;      // 1024 float4s per block
static constexpr int BLOCKS  = N4 / PER_BLK;          // 4096

__device__ __forceinline__ void lif4(const float4 xv, const float4 vv, const float4 iv,
                                     const float dt_tau, const float syn_k,
                                     float4& zr, float4& vr, float4& ir)
{
    {
        float vd = fmaf(dt_tau, iv.x - vv.x, vv.x);
        float z  = (vd - V_TH > 0.0f) ? 1.0f : 0.0f;
        zr.x = z;  vr.x = (z > 0.0f) ? 0.0f : vd;
        ir.x = (iv.x - syn_k * iv.x) + xv.x;
    }
    {
        float vd = fmaf(dt_tau, iv.y - vv.y, vv.y);
        float z  = (vd - V_TH > 0.0f) ? 1.0f : 0.0f;
        zr.y = z;  vr.y = (z > 0.0f) ? 0.0f : vd;
        ir.y = (iv.y - syn_k * iv.y) + xv.y;
    }
    {
        float vd = fmaf(dt_tau, iv.z - vv.z, vv.z);
        float z  = (vd - V_TH > 0.0f) ? 1.0f : 0.0f;
        zr.z = z;  vr.z = (z > 0.0f) ? 0.0f : vd;
        ir.z = (iv.z - syn_k * iv.z) + xv.z;
    }
    {
        float vd = fmaf(dt_tau, iv.w - vv.w, vv.w);
        float z  = (vd - V_TH > 0.0f) ? 1.0f : 0.0f;
        zr.w = z;  vr.w = (z > 0.0f) ? 0.0f : vd;
        ir.w = (iv.w - syn_k * iv.w) + xv.w;
    }
}

__global__ __launch_bounds__(THREADS)
void lif_step_kernel(const float4* __restrict__ x,
                     const float4* __restrict__ v0,
                     const float4* __restrict__ i0,
                     const float*  __restrict__ ps,
                     float4* __restrict__ z_out,
                     float4* __restrict__ v_out,
                     float4* __restrict__ i_out)
{
    const int base = blockIdx.x * PER_BLK + threadIdx.x;   // exact cover

    int idx[UNROLL];
    #pragma unroll
    for (int k = 0; k < UNROLL; k++) idx[k] = base + k * THREADS;

    // Front-batch all 12 loads (streaming: no reuse, evict-first).
    float4 xv[UNROLL], vv[UNROLL], iv[UNROLL];
    #pragma unroll
    for (int k = 0; k < UNROLL; k++) xv[k] = __ldcs(x  + idx[k]);
    #pragma unroll
    for (int k = 0; k < UNROLL; k++) vv[k] = __ldcs(v0 + idx[k]);
    #pragma unroll
    for (int k = 0; k < UNROLL; k++) iv[k] = __ldcs(i0 + idx[k]);

    const float syn_k = DT * TAU_SYN_INV;  // 0.2f, matching ref op order

    #pragma unroll
    for (int k = 0; k < UNROLL; k++) {
        // channel = (element_index / (H*W)) % C  ->  (float4_index >> 12) & 63
        const float dt_tau = DT * __ldg(ps + ((idx[k] >> 12) & 63));
        float4 zr, vr, ir;
        lif4(xv[k], vv[k], iv[k], dt_tau, syn_k, zr, vr, ir);
        __stcs(z_out + idx[k], zr);
        __stcs(v_out + idx[k], vr);
        __stcs(i_out + idx[k], ir);
    }
}

extern "C" void kernel_launch(void* const* d_in, const int* in_sizes, int n_in,
                              void* d_out, int out_size)
{
    const float4* x  = (const float4*)d_in[0];
    const float4* v0 = (const float4*)d_in[1];
    const float4* i0 = (const float4*)d_in[2];
    const float*  ps = (const float*)d_in[3];

    float* out = (float*)d_out;
    float4* z_out = (float4*)(out);
    float4* v_out = (float4*)(out + N_ELEMS);
    float4* i_out = (float4*)(out + 2 * N_ELEMS);

    lif_step_kernel<<<BLOCKS, THREADS>>>(x, v0, i0, ps, z_out, v_out, i_out);
}

// round 6
// speedup vs baseline: 1.0214x; 1.0066x over previous
#include <cuda_runtime.h>

// LIF neuron Euler step (TemporalReceptiveField), pure elementwise, HBM-bound.
// R5: UNROLL=3 (9 front-batched LDG.128) to maximize occ x MLP product:
//     ~48 regs -> ~62% occ, vs R3 (81% x 6) and R4 (40% x 12).

#define DT           0.001f
#define TAU_SYN_INV  200.0f
#define V_TH         1.0f

static constexpr int N_ELEMS = 16 * 64 * 128 * 128;   // 16,777,216
static constexpr int N4      = N_ELEMS / 4;           // 4,194,304 float4s (2^22)
static constexpr int THREADS = 256;
static constexpr int UNROLL  = 3;
static constexpr int PER_BLK = THREADS * UNROLL;      // 768 float4s per block
static constexpr int BLOCKS  = (N4 + PER_BLK - 1) / PER_BLK;  // 5462 (last block partial)

__device__ __forceinline__ void lif4(const float4 xv, const float4 vv, const float4 iv,
                                     const float dt_tau, const float syn_k,
                                     float4& zr, float4& vr, float4& ir)
{
    {
        float vd = fmaf(dt_tau, iv.x - vv.x, vv.x);
        float z  = (vd - V_TH > 0.0f) ? 1.0f : 0.0f;
        zr.x = z;  vr.x = (z > 0.0f) ? 0.0f : vd;
        ir.x = (iv.x - syn_k * iv.x) + xv.x;
    }
    {
        float vd = fmaf(dt_tau, iv.y - vv.y, vv.y);
        float z  = (vd - V_TH > 0.0f) ? 1.0f : 0.0f;
        zr.y = z;  vr.y = (z > 0.0f) ? 0.0f : vd;
        ir.y = (iv.y - syn_k * iv.y) + xv.y;
    }
    {
        float vd = fmaf(dt_tau, iv.z - vv.z, vv.z);
        float z  = (vd - V_TH > 0.0f) ? 1.0f : 0.0f;
        zr.z = z;  vr.z = (z > 0.0f) ? 0.0f : vd;
        ir.z = (iv.z - syn_k * iv.z) + xv.z;
    }
    {
        float vd = fmaf(dt_tau, iv.w - vv.w, vv.w);
        float z  = (vd - V_TH > 0.0f) ? 1.0f : 0.0f;
        zr.w = z;  vr.w = (z > 0.0f) ? 0.0f : vd;
        ir.w = (iv.w - syn_k * iv.w) + xv.w;
    }
}

__global__ __launch_bounds__(THREADS)
void lif_step_kernel(const float4* __restrict__ x,
                     const float4* __restrict__ v0,
                     const float4* __restrict__ i0,
                     const float*  __restrict__ ps,
                     float4* __restrict__ z_out,
                     float4* __restrict__ v_out,
                     float4* __restrict__ i_out)
{
    const int base = blockIdx.x * PER_BLK + threadIdx.x;

    int  idx[UNROLL];
    bool ok[UNROLL];
    #pragma unroll
    for (int k = 0; k < UNROLL; k++) {
        idx[k] = base + k * THREADS;
        ok[k]  = idx[k] < N4;
    }

    // Front-batch all loads (streaming: no reuse, evict-first).
    float4 xv[UNROLL], vv[UNROLL], iv[UNROLL];
    #pragma unroll
    for (int k = 0; k < UNROLL; k++) if (ok[k]) xv[k] = __ldcs(x  + idx[k]);
    #pragma unroll
    for (int k = 0; k < UNROLL; k++) if (ok[k]) vv[k] = __ldcs(v0 + idx[k]);
    #pragma unroll
    for (int k = 0; k < UNROLL; k++) if (ok[k]) iv[k] = __ldcs(i0 + idx[k]);

    const float syn_k = DT * TAU_SYN_INV;  // 0.2f, matching ref op order

    #pragma unroll
    for (int k = 0; k < UNROLL; k++) {
        if (!ok[k]) continue;
        // channel = (element_index / (H*W)) % C  ->  (float4_index >> 12) & 63
        const float dt_tau = DT * __ldg(ps + ((idx[k] >> 12) & 63));
        float4 zr, vr, ir;
        lif4(xv[k], vv[k], iv[k], dt_tau, syn_k, zr, vr, ir);
        __stcs(z_out + idx[k], zr);
        __stcs(v_out + idx[k], vr);
        __stcs(i_out + idx[k], ir);
    }
}

extern "C" void kernel_launch(void* const* d_in, const int* in_sizes, int n_in,
                              void* d_out, int out_size)
{
    const float4* x  = (const float4*)d_in[0];
    const float4* v0 = (const float4*)d_in[1];
    const float4* i0 = (const float4*)d_in[2];
    const float*  ps = (const float*)d_in[3];

    float* out = (float*)d_out;
    float4* z_out = (float4*)(out);
    float4* v_out = (float4*)(out + N_ELEMS);
    float4* i_out = (float4*)(out + 2 * N_ELEMS);

    lif_step_kernel<<<BLOCKS, THREADS>>>(x, v0, i0, ps, z_out, v_out, i_out);
}